// round 16
// baseline (speedup 1.0000x reference)
#include <cuda_runtime.h>
#include <cuda_fp16.h>
#include <math.h>

#define SZ_LOG 25
#define SZ (1u << SZ_LOG)          // 33554432
#define FD 30000000u               // FLAT_DIM
#define LOW_TILE 8192              // 2^13, low-pass tile

// Zero-padding structure: tiles [3663, 4096) of FWHT1's input are all-zero
// (theta padding), and h6a groups [58, 64) are entirely inside the zero tail.
#define LOW_GRID_FULL 4096
#define LOW_GRID_NZ   3663        // ceil(FD / LOW_TILE)
#define ZTAIL_START   (LOW_GRID_NZ * LOW_TILE)   // 30007296
#define H6A_GROUPS_NZ 58          // ceil(FD / 524288)

// fp16 range guard: FWHT2 intermediates reach std ~5e5, so pre-scale the
// second-transform data path by 2^-12 (exact in fp16) and undo at the end.
#define PRESCALE   (1.0f / 4096.0f)
#define UNPRESCALE 4096.0f

// Scratch (allocation-free rule): two fp16 ping-pong buffers, 64MB each.
__device__ __half g_h0[SZ];
__device__ __half g_h1[SZ];

// Side stream + events (static-init so context allocations precede the
// harness's device-memory baseline). Capture-legal use requires a proper
// fork: side-stream work must be downstream of an event recorded on the
// captured (default) stream.
struct SideStream {
    cudaStream_t s;
    cudaEvent_t  ev_fork, ev_join;
    SideStream() {
        cudaStreamCreateWithFlags(&s, cudaStreamNonBlocking);
        cudaEventCreateWithFlags(&ev_fork, cudaEventDisableTiming);
        cudaEventCreateWithFlags(&ev_join, cudaEventDisableTiming);
    }
};
static SideStream g_ss;

// Raw 2B gather, L2-only (random lines would waste L1), result as uint.
__device__ __forceinline__ unsigned ldg_u16_cg(const __half* p) {
    unsigned short r;
    asm volatile("ld.global.cg.u16 %0, [%1];" : "=h"(r) : "l"(p));
    return (unsigned)r;
}

// ---------------------------------------------------------------------------
// Fully-unrolled in-register FWHT over N floats
// ---------------------------------------------------------------------------
template <int N>
__device__ __forceinline__ void fwhtN(float* v) {
#pragma unroll
    for (int h = 1; h < N; h <<= 1) {
#pragma unroll
        for (int s = 0; s < N; s += 2 * h) {
#pragma unroll
            for (int k = 0; k < h; k++) {
                float a = v[s + k];
                float b = v[s + k + h];
                v[s + k]     = a + b;
                v[s + k + h] = a - b;
            }
        }
    }
}

// Shared swizzle: XORs bits 5..9 into the bank bits 0..4. Conflict-free for
// all three low-pass access patterns (scalar accesses ONLY — the XOR lands
// in the low bits, so runs are NOT contiguous and must not be vectorized).
__device__ __forceinline__ int sw(int a) { return a ^ ((a >> 5) & 31); }

// Zero-fill for the h0 tail (tiles skipped by k_low<0>): 16B per thread.
__global__ void k_zfill(__half* __restrict__ p, unsigned n16) {
    unsigned i = blockIdx.x * blockDim.x + threadIdx.x;
    if (i < n16) reinterpret_cast<uint4*>(p)[i] = make_uint4(0, 0, 0, 0);
}

// ---------------------------------------------------------------------------
// Low pass: butterflies on bits 0..12 over contiguous 8192-element tiles.
// 256 threads x 32 elements/thread.
// MODE 0 (stream-bound): x = pad(theta)*B; grid covers nonzero tiles only.
// MODE 1 (gather, l1tex-wavefront-bound): x = srcH[Pi[i]]*G[i]*PRESCALE;
//   32-deep gather pipeline via register aliasing, 32 warps/SM.
// Phases: fwht32 on bits 8..12 | fwht32 on bits 3..7 | fwht8 on bits 0..2.
// ---------------------------------------------------------------------------
template <int MODE>
__global__ __launch_bounds__(256, (MODE == 1 ? 4 : 3)) void k_low(
    const float*  __restrict__ theta, const float* __restrict__ Bv,
    const __half* __restrict__ srcH,  const int*   __restrict__ Pi,
    const float*  __restrict__ G,     __half*      __restrict__ dst)
{
    __shared__ float s[LOW_TILE];
    const int t = threadIdx.x;                       // 0..255
    const unsigned base = blockIdx.x * LOW_TILE;

    float v[32];
    if (MODE == 0) {
#pragma unroll
        for (int j = 0; j < 32; j++) {
            unsigned idx = base + (unsigned)j * 256u + (unsigned)t;
            float th = (idx < FD) ? __ldcs(&theta[idx]) : 0.0f;
            v[j] = th * __ldcs(&Bv[idx]);
        }
    } else {
        // Stage 1: 32 coalesced Pi loads, results parked in v[] as ints.
#pragma unroll
        for (int j = 0; j < 32; j++)
            v[j] = __int_as_float(__ldcs(&Pi[base + (unsigned)j * 256u + (unsigned)t]));
        // Stage 2: 32 independent random gathers, each overwriting its own
        // address register (max in-flight per warp).
#pragma unroll
        for (int j = 0; j < 32; j++)
            v[j] = __uint_as_float(ldg_u16_cg(&srcH[__float_as_int(v[j])]));
        // Stage 3: convert + multiply by G (fresh coalesced stream loads).
#pragma unroll
        for (int j = 0; j < 32; j++) {
            unsigned idx = base + (unsigned)j * 256u + (unsigned)t;
            float x = __half2float(__ushort_as_half(
                          (unsigned short)__float_as_uint(v[j])));
            v[j] = x * (__ldcs(&G[idx]) * PRESCALE);
        }
    }

    fwhtN<32>(v);  // bits 8..12  (e = j*256 + t)

#pragma unroll
    for (int j = 0; j < 32; j++) s[sw(j * 256 + t)] = v[j];
    __syncthreads();

    // Phase B: thread owns bits 3..7; fixed bits 0..2 = t&7, bits 8..12 = t>>3.
    {
        const int m = t >> 3, r = t & 7;
#pragma unroll
        for (int k = 0; k < 32; k++) v[k] = s[sw(m * 256 + k * 8 + r)];

        fwhtN<32>(v);  // bits 3..7

#pragma unroll
        for (int k = 0; k < 32; k++) s[sw(m * 256 + k * 8 + r)] = v[k];
    }
    __syncthreads();

    // Phase C: 4 octets per thread; fwht8 on bits 0..2, 16B coalesced stores.
    // Scalar smem reads (the swizzle scrambles low bits; see sw() note).
#pragma unroll
    for (int g = 0; g < 4; g++) {
        float w[8];
        const int ebase = g * 2048 + t * 8;
#pragma unroll
        for (int b = 0; b < 8; b++) w[b] = s[sw(ebase + b)];

        fwhtN<8>(w);   // bits 0..2

        __half h[8];
#pragma unroll
        for (int b = 0; b < 8; b++) h[b] = __float2half_rn(w[b]);

        uint4 pack = *reinterpret_cast<uint4*>(h);
        uint4* p = reinterpret_cast<uint4*>(&dst[base + (unsigned)ebase]);
        if (MODE == 1) __stcs(p, pack);   // h1 is a stream; protect gather-src L2
        else           *p = pack;         // h0 will be gathered: keep in L2
    }
}

// ---------------------------------------------------------------------------
// 6-bit streaming butterfly pass at element stride S.
// Each thread privately owns 64 elements {base + j*S}; warp loads are 64B
// contiguous runs. No shared memory, no barriers, pure MLP stream.
//   S = 8192   -> global bits 13..18
//   S = 524288 -> global bits 19..24
// FINAL=1: fp32 output truncated to FD, scaled by
//          UNPRESCALE / (divisor*sqrt(FD/SZ)).
// ---------------------------------------------------------------------------
template <unsigned S, int FINAL>
__global__ __launch_bounds__(256) void k_h6(
    __half* __restrict__ buf, float* __restrict__ out,
    const float* __restrict__ divisor)
{
    const unsigned t     = threadIdx.x;
    const unsigned cpg   = S / 256u;                 // chunks per 64*S group
    const unsigned group = blockIdx.x / cpg;
    const unsigned chunk = blockIdx.x % cpg;
    const unsigned base  = group * (S * 64u) + chunk * 256u + t;

    float v[64];
#pragma unroll
    for (int j = 0; j < 64; j++)
        v[j] = __half2float(__ldcg(&buf[base + (unsigned)j * S]));

    fwhtN<64>(v);

    if (FINAL) {
        const float scale = UNPRESCALE / (divisor[0] * sqrtf((float)FD / (float)SZ));
#pragma unroll
        for (int j = 0; j < 64; j++) {
            unsigned idx = base + (unsigned)j * S;
            if (idx < FD) __stcs(&out[idx], v[j] * scale);
        }
    } else {
#pragma unroll
        for (int j = 0; j < 64; j++)
            buf[base + (unsigned)j * S] = __float2half_rn(v[j]);
    }
}

// ---------------------------------------------------------------------------
// kernel_launch: 7 graph-capturable launches; zfill runs on a side stream
// properly forked from (and joined back into) the captured stream.
// ---------------------------------------------------------------------------
extern "C" void kernel_launch(void* const* d_in, const int* in_sizes, int n_in,
                              void* d_out, int out_size)
{
    const float* theta   = (const float*)d_in[0];
    const float* G       = (const float*)d_in[1];
    const float* B       = (const float*)d_in[2];
    const float* divisor = (const float*)d_in[3];
    const int*   Pi      = (const int*)d_in[4];
    float*       out     = (float*)d_out;

    __half *h0, *h1;
    cudaGetSymbolAddress((void**)&h0, g_h0);
    cudaGetSymbolAddress((void**)&h1, g_h1);

    const int h6_grid = SZ / (64 * 256);       // 2048
    const int h6a_grid = H6A_GROUPS_NZ * 32;   // 1856: skip all-zero groups

    // Fork: root the side stream in the captured stream, zero the h0 tail
    // there (disjoint from k_low<0>'s output range), join before h6a.
    const unsigned ztail16 = (SZ - ZTAIL_START) / 8;  // 16B units
    cudaEventRecord(g_ss.ev_fork, 0);
    cudaStreamWaitEvent(g_ss.s, g_ss.ev_fork, 0);
    k_zfill<<<(ztail16 + 255) / 256, 256, 0, g_ss.s>>>(h0 + ZTAIL_START, ztail16);
    cudaEventRecord(g_ss.ev_join, g_ss.s);

    // FWHT #1: pad*B + bits 0..12 -> h0 (nonzero tiles only);
    //          bits 13..18 (skip zero groups); bits 19..24 (in place).
    k_low<0><<<LOW_GRID_NZ, 256>>>(theta, B, nullptr, nullptr, nullptr, h0);
    cudaStreamWaitEvent(0, g_ss.ev_join, 0);
    k_h6<8192u,   0><<<h6a_grid, 256>>>(h0, nullptr, nullptr);
    k_h6<524288u, 0><<<h6_grid, 256>>>(h0, nullptr, nullptr);

    // FWHT #2: gather(Pi)*G (pre-scaled) + bits 0..12 -> h1;
    //          bits 13..18; bits 19..24 + final scale.
    k_low<1><<<LOW_GRID_FULL, 256>>>(nullptr, nullptr, h0, Pi, G, h1);
    k_h6<8192u,   0><<<h6_grid, 256>>>(h1, nullptr, nullptr);
    k_h6<524288u, 1><<<h6_grid, 256>>>(h1, out, divisor);
}

// round 17
// speedup vs baseline: 1.0174x; 1.0174x over previous
#include <cuda_runtime.h>
#include <cuda_fp16.h>
#include <math.h>

#define SZ_LOG 25
#define SZ (1u << SZ_LOG)          // 33554432
#define FD 30000000u               // FLAT_DIM
#define LOW_TILE 8192              // 2^13, low-pass tile

// Zero-padding structure: tiles [3663, 4096) of FWHT1's input are all-zero
// (theta padding), and h6a groups [58, 64) are entirely inside the zero tail.
#define LOW_GRID_FULL 4096
#define LOW_GRID_NZ   3663        // ceil(FD / LOW_TILE)
#define H6A_GROUPS_NZ 58          // ceil(FD / 524288)

// fp16 range guard: FWHT2 intermediates reach std ~5e5, so pre-scale the
// second-transform data path by 2^-12 (exact in fp16) and undo at the end.
#define PRESCALE   (1.0f / 4096.0f)
#define UNPRESCALE 4096.0f

// Scratch (allocation-free rule): two fp16 ping-pong buffers, 64MB each.
__device__ __half g_h0[SZ];
__device__ __half g_h1[SZ];

// Raw 2B gather, L2-only (random lines would waste L1), result as uint.
__device__ __forceinline__ unsigned ldg_u16_cg(const __half* p) {
    unsigned short r;
    asm volatile("ld.global.cg.u16 %0, [%1];" : "=h"(r) : "l"(p));
    return (unsigned)r;
}

// ---------------------------------------------------------------------------
// Fully-unrolled in-register FWHT over N floats
// ---------------------------------------------------------------------------
template <int N>
__device__ __forceinline__ void fwhtN(float* v) {
#pragma unroll
    for (int h = 1; h < N; h <<= 1) {
#pragma unroll
        for (int s = 0; s < N; s += 2 * h) {
#pragma unroll
            for (int k = 0; k < h; k++) {
                float a = v[s + k];
                float b = v[s + k + h];
                v[s + k]     = a + b;
                v[s + k + h] = a - b;
            }
        }
    }
}

// Shared swizzle: XORs bits 5..9 into the bank bits 0..4. Conflict-free for
// all three low-pass access patterns (scalar accesses ONLY — the XOR lands
// in the low bits, so runs are NOT contiguous and must not be vectorized).
__device__ __forceinline__ int sw(int a) { return a ^ ((a >> 5) & 31); }

// ---------------------------------------------------------------------------
// Low pass: butterflies on bits 0..12 over contiguous 8192-element tiles.
// 256 threads x 32 elements/thread.
// MODE 0 (stream-bound): x = pad(theta)*B. Tiles >= LOW_GRID_NZ are all-zero
//   (theta padding): store-only fast path, no loads, no FWHT.
// MODE 1 (gather, l1tex-wavefront-bound): x = srcH[Pi[i]]*G[i]*PRESCALE;
//   32-deep gather pipeline via register aliasing, 32 warps/SM.
// Phases: fwht32 on bits 8..12 | fwht32 on bits 3..7 | fwht8 on bits 0..2.
// ---------------------------------------------------------------------------
template <int MODE>
__global__ __launch_bounds__(256, (MODE == 1 ? 4 : 3)) void k_low(
    const float*  __restrict__ theta, const float* __restrict__ Bv,
    const __half* __restrict__ srcH,  const int*   __restrict__ Pi,
    const float*  __restrict__ G,     __half*      __restrict__ dst)
{
    __shared__ float s[LOW_TILE];
    const int t = threadIdx.x;                       // 0..255
    const unsigned base = blockIdx.x * LOW_TILE;

    if (MODE == 0 && blockIdx.x >= LOW_GRID_NZ) {
        // Zero tail: FWHT(0) = 0. 32 x 16B stores per thread, done.
        const uint4 z = make_uint4(0, 0, 0, 0);
#pragma unroll
        for (int g = 0; g < 4; g++)
            reinterpret_cast<uint4*>(&dst[base + (unsigned)(g * 2048 + t * 8)])[0] = z;
        return;
    }

    float v[32];
    if (MODE == 0) {
#pragma unroll
        for (int j = 0; j < 32; j++) {
            unsigned idx = base + (unsigned)j * 256u + (unsigned)t;
            float th = (idx < FD) ? __ldcs(&theta[idx]) : 0.0f;
            v[j] = th * __ldcs(&Bv[idx]);
        }
    } else {
        // Stage 1: 32 coalesced Pi loads, results parked in v[] as ints.
#pragma unroll
        for (int j = 0; j < 32; j++)
            v[j] = __int_as_float(__ldcs(&Pi[base + (unsigned)j * 256u + (unsigned)t]));
        // Stage 2: 32 independent random gathers, each overwriting its own
        // address register (max in-flight per warp).
#pragma unroll
        for (int j = 0; j < 32; j++)
            v[j] = __uint_as_float(ldg_u16_cg(&srcH[__float_as_int(v[j])]));
        // Stage 3: convert + multiply by G (fresh coalesced stream loads).
#pragma unroll
        for (int j = 0; j < 32; j++) {
            unsigned idx = base + (unsigned)j * 256u + (unsigned)t;
            float x = __half2float(__ushort_as_half(
                          (unsigned short)__float_as_uint(v[j])));
            v[j] = x * (__ldcs(&G[idx]) * PRESCALE);
        }
    }

    fwhtN<32>(v);  // bits 8..12  (e = j*256 + t)

#pragma unroll
    for (int j = 0; j < 32; j++) s[sw(j * 256 + t)] = v[j];
    __syncthreads();

    // Phase B: thread owns bits 3..7; fixed bits 0..2 = t&7, bits 8..12 = t>>3.
    {
        const int m = t >> 3, r = t & 7;
#pragma unroll
        for (int k = 0; k < 32; k++) v[k] = s[sw(m * 256 + k * 8 + r)];

        fwhtN<32>(v);  // bits 3..7

#pragma unroll
        for (int k = 0; k < 32; k++) s[sw(m * 256 + k * 8 + r)] = v[k];
    }
    __syncthreads();

    // Phase C: 4 octets per thread; fwht8 on bits 0..2, 16B coalesced stores.
    // Scalar smem reads (the swizzle scrambles low bits; see sw() note).
#pragma unroll
    for (int g = 0; g < 4; g++) {
        float w[8];
        const int ebase = g * 2048 + t * 8;
#pragma unroll
        for (int b = 0; b < 8; b++) w[b] = s[sw(ebase + b)];

        fwhtN<8>(w);   // bits 0..2

        __half h[8];
#pragma unroll
        for (int b = 0; b < 8; b++) h[b] = __float2half_rn(w[b]);

        uint4 pack = *reinterpret_cast<uint4*>(h);
        uint4* p = reinterpret_cast<uint4*>(&dst[base + (unsigned)ebase]);
        if (MODE == 1) __stcs(p, pack);   // h1 is a stream; protect gather-src L2
        else           *p = pack;         // h0 will be gathered: keep in L2
    }
}

// ---------------------------------------------------------------------------
// 6-bit streaming butterfly pass at element stride S.
// Each thread privately owns 64 elements {base + j*S}; warp loads are 64B
// contiguous runs. No shared memory, no barriers, pure MLP stream.
//   S = 8192   -> global bits 13..18
//   S = 524288 -> global bits 19..24
// FINAL=1: fp32 output truncated to FD, scaled by
//          UNPRESCALE / (divisor*sqrt(FD/SZ)).
// ---------------------------------------------------------------------------
template <unsigned S, int FINAL>
__global__ __launch_bounds__(256) void k_h6(
    __half* __restrict__ buf, float* __restrict__ out,
    const float* __restrict__ divisor)
{
    const unsigned t     = threadIdx.x;
    const unsigned cpg   = S / 256u;                 // chunks per 64*S group
    const unsigned group = blockIdx.x / cpg;
    const unsigned chunk = blockIdx.x % cpg;
    const unsigned base  = group * (S * 64u) + chunk * 256u + t;

    float v[64];
#pragma unroll
    for (int j = 0; j < 64; j++)
        v[j] = __half2float(__ldcg(&buf[base + (unsigned)j * S]));

    fwhtN<64>(v);

    if (FINAL) {
        const float scale = UNPRESCALE / (divisor[0] * sqrtf((float)FD / (float)SZ));
#pragma unroll
        for (int j = 0; j < 64; j++) {
            unsigned idx = base + (unsigned)j * S;
            if (idx < FD) __stcs(&out[idx], v[j] * scale);
        }
    } else {
#pragma unroll
        for (int j = 0; j < 64; j++)
            buf[base + (unsigned)j * S] = __float2half_rn(v[j]);
    }
}

// ---------------------------------------------------------------------------
// kernel_launch: 6 graph-capturable launches, single stream, no allocs.
// ---------------------------------------------------------------------------
extern "C" void kernel_launch(void* const* d_in, const int* in_sizes, int n_in,
                              void* d_out, int out_size)
{
    const float* theta   = (const float*)d_in[0];
    const float* G       = (const float*)d_in[1];
    const float* B       = (const float*)d_in[2];
    const float* divisor = (const float*)d_in[3];
    const int*   Pi      = (const int*)d_in[4];
    float*       out     = (float*)d_out;

    __half *h0, *h1;
    cudaGetSymbolAddress((void**)&h0, g_h0);
    cudaGetSymbolAddress((void**)&h1, g_h1);

    const int h6_grid = SZ / (64 * 256);       // 2048
    const int h6a_grid = H6A_GROUPS_NZ * 32;   // 1856: skip all-zero groups

    // FWHT #1: pad*B + bits 0..12 -> h0 (zero tail folded into the kernel);
    //          bits 13..18 (skip zero groups); bits 19..24 (in place).
    k_low<0><<<LOW_GRID_FULL, 256>>>(theta, B, nullptr, nullptr, nullptr, h0);
    k_h6<8192u,   0><<<h6a_grid, 256>>>(h0, nullptr, nullptr);
    k_h6<524288u, 0><<<h6_grid, 256>>>(h0, nullptr, nullptr);

    // FWHT #2: gather(Pi)*G (pre-scaled) + bits 0..12 -> h1;
    //          bits 13..18; bits 19..24 + final scale.
    k_low<1><<<LOW_GRID_FULL, 256>>>(nullptr, nullptr, h0, Pi, G, h1);
    k_h6<8192u,   0><<<h6_grid, 256>>>(h1, nullptr, nullptr);
    k_h6<524288u, 1><<<h6_grid, 256>>>(h1, out, divisor);
}